// round 12
// baseline (speedup 1.0000x reference)
#include <cuda_runtime.h>
#include <cuda_fp16.h>
#include <cstdint>
#include <math.h>

#define NB   512
#define DD   2048
#define HID  8192
#define MT   (NB*64)

typedef __half hf;
typedef uint16_t u16;

// ---------------- scratch ----------------------------------------------------
__device__ hf    g_wq [(size_t)3*DD*DD];
__device__ hf    g_wo [(size_t)DD*DD];
__device__ hf    g_w1 [(size_t)HID*DD];
__device__ hf    g_w2 [(size_t)DD*HID];
__device__ hf    g_wi [(size_t)DD*DD];
__device__ hf    g_wp [(size_t)DD*DD];
__device__ hf    g_x  [(size_t)MT*DD];
__device__ hf    g_y  [(size_t)MT*DD];
__device__ hf    g_qkv[(size_t)MT*3*DD];
__device__ hf    g_z  [(size_t)MT*DD];
__device__ hf    g_h  [(size_t)MT*HID];
__device__ hf    g_pf [(size_t)NB*DD];
__device__ float g_tok[(size_t)MT*DD];
__device__ float g_ps [MT];
__device__ float g_pooled[(size_t)NB*DD];
__device__ float g_pout  [(size_t)NB*DD];

// ---------------- helpers ----------------------------------------------------
__device__ __forceinline__ uint32_t s2u(const void* p){
    uint32_t a;
    asm("{ .reg .u64 t; cvta.to.shared.u64 t, %1; cvt.u32.u64 %0, t; }" : "=r"(a) : "l"(p));
    return a;
}
__device__ __forceinline__ void cpa16(uint32_t d, const void* s){
    asm volatile("cp.async.cg.shared.global [%0], [%1], 16;" :: "r"(d), "l"(s));
}
__device__ __forceinline__ void ldm4(uint32_t* r, uint32_t a){
    asm volatile("ldmatrix.sync.aligned.m8n8.x4.shared.b16 {%0,%1,%2,%3}, [%4];"
        : "=r"(r[0]), "=r"(r[1]), "=r"(r[2]), "=r"(r[3]) : "r"(a));
}
__device__ __forceinline__ void mmaf16(float* d, const uint32_t* a, uint32_t b0, uint32_t b1){
    asm volatile(
        "mma.sync.aligned.m16n8k16.row.col.f32.f16.f16.f32 "
        "{%0,%1,%2,%3},{%4,%5,%6,%7},{%8,%9},{%0,%1,%2,%3};"
        : "+f"(d[0]), "+f"(d[1]), "+f"(d[2]), "+f"(d[3])
        : "r"(a[0]), "r"(a[1]), "r"(a[2]), "r"(a[3]), "r"(b0), "r"(b1));
}

// ---------------- pipelined fp16 GEMM: C=A@W^T + epi -------------------------
// CTA tile 128x128x64, warp 32x64 (8 warps = 4m x 2n), 3-stage cp.async ring,
// 2 CTAs/SM, smem-staged coalesced epilogue.
// EPI: 0 +bias ; 1 GELU ; 2 resid+gam*.  OUTH: fp16 out else fp32.
#define STH 72
#define STG (128*STH)
#define STAGEB (2*STG*2)
#define SM_G (3*STAGEB)
#define CSTRIDE 129
template<int EPI, bool OUTH>
__global__ void __launch_bounds__(256, 2)
gemm_p(const hf* __restrict__ A, const hf* __restrict__ W,
       const float* __restrict__ bias, void* __restrict__ Cv,
       const float* __restrict__ resid, const float* __restrict__ gam,
       int M, int N, int K)
{
    extern __shared__ u16 smb[];
    const uint32_t sbase = s2u(smb);

    const int tid = threadIdx.x, wid = tid>>5, lane = tid&31;
    const int wm = wid&3, wn = wid>>2;
    const int m0 = blockIdx.y<<7, n0 = blockIdx.x<<7;
    const int g = lane>>2, qt = lane&3;

    float acc[2][8][4];
#pragma unroll
    for (int i=0;i<2;i++)
#pragma unroll
        for (int j=0;j<8;j++)
#pragma unroll
            for (int c=0;c<4;c++) acc[i][j][c]=0.f;

    const int T = K>>6;
    auto stage = [&](int t, int s){
        const int kt = t<<6;
        const uint32_t ob = sbase + (uint32_t)s*STAGEB;
#pragma unroll
        for (int i=0;i<4;i++){
            int id = tid + i*256, rr = id>>3, c8 = id&7;
            uint32_t so = rr*144 + c8*16;
            const size_t go = (size_t)rr*K + kt + c8*8;
            cpa16(ob + so,           A + (size_t)m0*K + go);
            cpa16(ob + STG*2 + so,   W + (size_t)n0*K + go);
        }
        asm volatile("cp.async.commit_group;" ::: "memory");
    };

    stage(0, 0);
    stage(1, 1);
    int s = 0, s2 = 2;
    for (int t=0; t<T; t++){
        if (t+1 < T) asm volatile("cp.async.wait_group 1;" ::: "memory");
        else         asm volatile("cp.async.wait_group 0;" ::: "memory");
        __syncthreads();
        if (t+2 < T) stage(t+2, s2);

        const uint32_t ab = sbase + (uint32_t)s*STAGEB;
        const uint32_t bb = ab + STG*2;

        const int arow = wm*32 + (lane&15);
        const int brow = wn*64 + ((lane>>4)<<3) + (lane&7);
        const int acol8 = (lane>>4)*8;
        const int bcol8 = ((lane>>3)&1)*8;
#pragma unroll
        for (int ks=0; ks<4; ks++){
            uint32_t af[2][4], bfr[4][4];
            ldm4(af[0], ab + (arow*STH + ks*16 + acol8)*2);
            ldm4(af[1], ab + ((arow+16)*STH + ks*16 + acol8)*2);
#pragma unroll
            for (int p=0;p<4;p++)
                ldm4(bfr[p], bb + ((brow + p*16)*STH + ks*16 + bcol8)*2);
#pragma unroll
            for (int mt=0;mt<2;mt++)
#pragma unroll
                for (int nt=0;nt<8;nt++)
                    mmaf16(acc[mt][nt], af[mt], bfr[nt>>1][(nt&1)*2], bfr[nt>>1][(nt&1)*2+1]);
        }
        s  = (s ==2)?0:s +1;
        s2 = (s2==2)?0:s2+1;
    }

    // ---- phase 2 epilogue: stage acc in smem, then coalesced global IO ----
    __syncthreads();
    float* cs = (float*)smb;
#pragma unroll
    for (int mt=0;mt<2;mt++)
#pragma unroll
        for (int nt=0;nt<8;nt++)
#pragma unroll
            for (int c=0;c<4;c++){
                int rl = wm*32 + mt*16 + g + ((c>>1)<<3);
                int cl = wn*64 + nt*8 + qt*2 + (c&1);
                cs[rl*CSTRIDE + cl] = acc[mt][nt][c];
            }
    __syncthreads();

    const float gv = (EPI==2) ? gam[0] : 0.f;
#pragma unroll 4
    for (int it=0; it<32; it++){
        int idx = it*256 + tid;
        int rl = idx>>6, cp2 = (idx&63)*2;
        float v0 = cs[rl*CSTRIDE + cp2];
        float v1 = cs[rl*CSTRIDE + cp2 + 1];
        const float* bp = bias + n0 + cp2;
        v0 += bp[0]; v1 += bp[1];
        if (EPI==1){
            v0 = 0.5f*v0*(1.f + erff(v0*0.70710678118654752f));
            v1 = 0.5f*v1*(1.f + erff(v1*0.70710678118654752f));
        }
        size_t go = (size_t)(m0+rl)*N + n0 + cp2;
        if (EPI==2){
            float2 rv = *(const float2*)(resid + go);
            v0 = rv.x + gv*v0; v1 = rv.y + gv*v1;
        }
        if (OUTH) *(__half2*)((hf*)Cv + go) = __floats2half2_rn(v0, v1);
        else      *(float2*)((float*)Cv + go) = make_float2(v0, v1);
    }
}

// ---------------- fused prep: xT + ALL weight conversions (one launch) -------
#define NQ  ((long)3*DD*DD)
#define NO  ((long)DD*DD)
#define NF  ((long)HID*DD)
#define XTBLK (32*NB)                 // 16384 transpose blocks
__global__ void __launch_bounds__(256)
prep_k(const float* __restrict__ x,
       const float* __restrict__ qkvw, const float* __restrict__ outw,
       const float* __restrict__ f1, const float* __restrict__ f2,
       const float* __restrict__ inw, const float* __restrict__ ppw,
       hf* __restrict__ xo,
       hf* __restrict__ wq, hf* __restrict__ wo, hf* __restrict__ w1,
       hf* __restrict__ w2, hf* __restrict__ wi, hf* __restrict__ wp)
{
    __shared__ float T[64][65];
    const int tid = threadIdx.x;
    if (blockIdx.x < XTBLK){
        const int b = blockIdx.x >> 5, c0 = (blockIdx.x & 31)*64;
        {
            const int sx = tid&63, cc = tid>>6;
            const float* xp = x + ((size_t)b*DD + c0)*64;
#pragma unroll
            for (int p=0;p<16;p++){ int c = cc + p*4; T[c][sx] = xp[(size_t)c*64 + sx]; }
        }
        __syncthreads();
        {
            const int c = tid&63, s4 = tid>>6;
#pragma unroll
            for (int p=0;p<16;p++){
                int ss = s4 + p*4;
                xo[((size_t)b*64 + ss)*DD + c0 + c] = __float2half_rn(T[c][ss]);
            }
        }
        return;
    }
    long i = ((long)(blockIdx.x - XTBLK)*256 + tid)*4;
    const long e0=NQ, e1=e0+NO, e2=e1+NF, e3=e2+NF, e4=e3+NO, e5=e4+NO;
    const float* s; hf* d; long j;
    if      (i < e0){ s=qkvw; d=wq; j=i; }
    else if (i < e1){ s=outw; d=wo; j=i-e0; }
    else if (i < e2){ s=f1;   d=w1; j=i-e1; }
    else if (i < e3){ s=f2;   d=w2; j=i-e2; }
    else if (i < e4){ s=inw;  d=wi; j=i-e3; }
    else if (i < e5){ s=ppw;  d=wp; j=i-e4; }
    else return;
    float4 v = *(const float4*)(s+j);
    d[j]=__float2half_rn(v.x); d[j+1]=__float2half_rn(v.y);
    d[j+2]=__float2half_rn(v.z); d[j+3]=__float2half_rn(v.w);
}

// ---------------- LayerNorm fp32 -> fp16 -------------------------------------
__global__ void __launch_bounds__(256)
ln_k(const float* __restrict__ src, const float* __restrict__ gw,
     const float* __restrict__ bw, hf* __restrict__ dst)
{
    __shared__ float sb[16];
    const int row = blockIdx.x, tid = threadIdx.x;
    const float* p = src + (size_t)row*DD;
    float v[8], s=0.f, q=0.f;
#pragma unroll
    for (int i=0;i<8;i++){ v[i]=p[tid+256*i]; s+=v[i]; q+=v[i]*v[i]; }
#pragma unroll
    for (int o=16;o;o>>=1){ s+=__shfl_xor_sync(~0u,s,o); q+=__shfl_xor_sync(~0u,q,o); }
    if ((tid&31)==0){ sb[tid>>5]=s; sb[8+(tid>>5)]=q; }
    __syncthreads();
    s=0.f; q=0.f;
#pragma unroll
    for (int w=0;w<8;w++){ s+=sb[w]; q+=sb[8+w]; }
    float mu = s*(1.f/DD), var = q*(1.f/DD)-mu*mu, rstd = rsqrtf(var+1e-5f);
#pragma unroll
    for (int i=0;i<8;i++){
        int c = tid+256*i;
        dst[(size_t)row*DD+c] = __float2half_rn((v[i]-mu)*rstd*gw[c]+bw[c]);
    }
}

// ---------------- fused attention per (b,h) ----------------------------------
#define ATTN_SMF (64*257 + 32*257 + 64*65 + 240)
__global__ void __launch_bounds__(256)
attn_k(const hf* __restrict__ qkv, const float* __restrict__ relb, hf* __restrict__ z)
{
    extern __shared__ float smf[];
    float* Qs = smf;
    float* KV = smf + 64*257;
    float* Ss = KV + 32*257;
    float* bs = Ss + 64*65;

    const int tid = threadIdx.x;
    const int bb = blockIdx.x>>3, h = blockIdx.x&7;
    const size_t base = (size_t)bb*64*6144 + h*256;

    for (int i=tid;i<225;i+=256) bs[i] = relb[h*225+i];
    for (int l=0;l<64;l++)
        Qs[l*257+tid] = __half2float(qkv[base + (size_t)l*6144 + tid]);
    __syncthreads();

    const int ty = tid>>4, tx = tid&15;
    for (int c=0;c<2;c++){
        for (int j=0;j<32;j++)
            KV[j*257+tid] = __half2float(qkv[base + (size_t)(c*32+j)*6144 + 2048 + tid]);
        __syncthreads();
        float a[4][2] = {};
        for (int k=0;k<256;k++){
            float k0 = KV[(2*tx)*257+k], k1 = KV[(2*tx+1)*257+k];
#pragma unroll
            for (int i=0;i<4;i++){
                float qv = Qs[(4*ty+i)*257+k];
                a[i][0] += qv*k0; a[i][1] += qv*k1;
            }
        }
#pragma unroll
        for (int i=0;i<4;i++)
#pragma unroll
            for (int j=0;j<2;j++){
                int row = 4*ty+i, col = c*32+2*tx+j;
                int rel = ((row>>3)-(col>>3)+7)*15 + ((row&7)-(col&7)+7);
                Ss[row*65+col] = a[i][j]*0.0625f + bs[rel];
            }
        __syncthreads();
    }
    {
        int w = tid>>5, lane = tid&31;
        for (int rr=0;rr<8;rr++){
            int row = w*8+rr;
            float v0 = Ss[row*65+lane], v1 = Ss[row*65+32+lane];
            float m = fmaxf(v0, v1);
#pragma unroll
            for (int o=16;o;o>>=1) m = fmaxf(m, __shfl_xor_sync(~0u, m, o));
            float e0 = expf(v0-m), e1 = expf(v1-m), ss = e0+e1;
#pragma unroll
            for (int o=16;o;o>>=1) ss += __shfl_xor_sync(~0u, ss, o);
            float inv = 1.f/ss;
            Ss[row*65+lane] = e0*inv; Ss[row*65+32+lane] = e1*inv;
        }
    }
    __syncthreads();

    float o[4][16];
#pragma unroll
    for (int i=0;i<4;i++)
#pragma unroll
        for (int j=0;j<16;j++) o[i][j]=0.f;
    for (int c=0;c<2;c++){
        for (int j=0;j<32;j++)
            KV[j*257+tid] = __half2float(qkv[base + (size_t)(c*32+j)*6144 + 4096 + tid]);
        __syncthreads();
        for (int j32=0;j32<32;j32++){
            float pv[4];
#pragma unroll
            for (int i=0;i<4;i++) pv[i] = Ss[(4*ty+i)*65 + c*32 + j32];
#pragma unroll
            for (int jc=0;jc<16;jc++){
                int jj = (jc+tx)&15;
                float vv = KV[j32*257 + 16*tx + jj];
#pragma unroll
                for (int i=0;i<4;i++) o[i][jj] += pv[i]*vv;
            }
        }
        __syncthreads();
    }
    const size_t zb = ((size_t)bb*64)*2048 + h*256;
#pragma unroll
    for (int i=0;i<4;i++)
#pragma unroll
        for (int jj=0;jj<16;jj++)
            z[zb + (size_t)(4*ty+i)*2048 + 16*tx + jj] = __float2half_rn(o[i][jj]);
}

// ---------------- pooling ----------------------------------------------------
__global__ void __launch_bounds__(256)
poolscore_k(const float* __restrict__ tok, const float* __restrict__ q,
            const float* __restrict__ gw, const float* __restrict__ bw,
            float* __restrict__ out)
{
    __shared__ float sb[40];
    const int row = blockIdx.x, tid = threadIdx.x;
    const float* p = tok + (size_t)row*DD;
    float s=0, sq=0, sqgt=0, sqg=0, sqb=0;
#pragma unroll
    for (int i=0;i<8;i++){
        int c = tid+256*i;
        float tv = p[c], qg = q[c]*gw[c];
        s+=tv; sq+=tv*tv; sqgt+=qg*tv; sqg+=qg; sqb+=q[c]*bw[c];
    }
#pragma unroll
    for (int o=16;o;o>>=1){
        s+=__shfl_xor_sync(~0u,s,o); sq+=__shfl_xor_sync(~0u,sq,o);
        sqgt+=__shfl_xor_sync(~0u,sqgt,o); sqg+=__shfl_xor_sync(~0u,sqg,o);
        sqb+=__shfl_xor_sync(~0u,sqb,o);
    }
    int w = tid>>5;
    if ((tid&31)==0){ sb[w]=s; sb[8+w]=sq; sb[16+w]=sqgt; sb[24+w]=sqg; sb[32+w]=sqb; }
    __syncthreads();
    if (tid==0){
        s=sq=sqgt=sqg=sqb=0.f;
        for (int i=0;i<8;i++){ s+=sb[i]; sq+=sb[8+i]; sqgt+=sb[16+i]; sqg+=sb[24+i]; sqb+=sb[32+i]; }
        float mu = s*(1.f/DD), var = sq*(1.f/DD)-mu*mu, rstd = rsqrtf(var+1e-5f);
        out[row] = (rstd*(sqgt-mu*sqg)+sqb)*0.022097086912079608f;
    }
}
__global__ void __launch_bounds__(256)
poolcomb_k(const float* __restrict__ tok, const float* __restrict__ ps,
           float* __restrict__ pooled, hf* __restrict__ pooledh)
{
    __shared__ float pr[64];
    const int b = blockIdx.x, tid = threadIdx.x;
    if (tid==0){
        float m = -1e30f;
        for (int l=0;l<64;l++) m = fmaxf(m, ps[b*64+l]);
        float ss = 0.f;
        for (int l=0;l<64;l++){ pr[l] = expf(ps[b*64+l]-m); ss += pr[l]; }
        float inv = 1.f/ss;
        for (int l=0;l<64;l++) pr[l] *= inv;
    }
    __syncthreads();
    float acc[8] = {};
    for (int l=0;l<64;l++){
        float w = pr[l];
        const float* tp = tok + ((size_t)b*64+l)*DD;
#pragma unroll
        for (int i=0;i<8;i++) acc[i] += w*tp[tid+256*i];
    }
#pragma unroll
    for (int i=0;i<8;i++){
        pooled[(size_t)b*DD + tid+256*i] = acc[i];
        pooledh[(size_t)b*DD + tid+256*i] = __float2half_rn(acc[i]);
    }
}
__global__ void __launch_bounds__(256)
norm_k(const float* __restrict__ pin, float* __restrict__ out)
{
    __shared__ float sb[8];
    const int b = blockIdx.x, tid = threadIdx.x;
    const float* p = pin + (size_t)b*DD;
    float v[8], s = 0.f;
#pragma unroll
    for (int i=0;i<8;i++){ v[i]=p[tid+256*i]; s+=v[i]*v[i]; }
#pragma unroll
    for (int o=16;o;o>>=1) s += __shfl_xor_sync(~0u, s, o);
    if ((tid&31)==0) sb[tid>>5]=s;
    __syncthreads();
    s=0.f;
#pragma unroll
    for (int w=0;w<8;w++) s += sb[w];
    float sc = 1.f/fmaxf(sqrtf(s), 1e-12f);
#pragma unroll
    for (int i=0;i<8;i++) out[(size_t)b*DD + tid+256*i] = v[i]*sc;
}

// ---------------- launch ------------------------------------------------------
extern "C" void kernel_launch(void* const* d_in, const int* in_sizes, int n_in,
                              void* d_out, int out_size)
{
    const float* x     = (const float*)d_in[0];
    const float* in_w  = (const float*)d_in[1];
    const float* in_b  = (const float*)d_in[2];
    const float* qkv_w = (const float*)d_in[3];
    const float* qkv_b = (const float*)d_in[4];
    const float* out_w = (const float*)d_in[5];
    const float* out_b = (const float*)d_in[6];
    const float* relb  = (const float*)d_in[7];
    const float* n1g   = (const float*)d_in[8];
    const float* n1b   = (const float*)d_in[9];
    const float* n2g   = (const float*)d_in[10];
    const float* n2b   = (const float*)d_in[11];
    const float* fc1w  = (const float*)d_in[12];
    const float* fc1b  = (const float*)d_in[13];
    const float* fc2w  = (const float*)d_in[14];
    const float* fc2b  = (const float*)d_in[15];
    const float* ga    = (const float*)d_in[16];
    const float* gm    = (const float*)d_in[17];
    const float* pq    = (const float*)d_in[18];
    const float* png   = (const float*)d_in[19];
    const float* pnb   = (const float*)d_in[20];
    const float* ppw   = (const float*)d_in[21];
    const float* ppb   = (const float*)d_in[22];
    float* out = (float*)d_out;

    hf *wq,*wo,*w1,*w2,*wi,*wp,*xh,*y,*qkvb,*z,*hb,*pf;
    float *tok,*ps,*pooled,*pout;
    cudaGetSymbolAddress((void**)&wq, g_wq);  cudaGetSymbolAddress((void**)&wo, g_wo);
    cudaGetSymbolAddress((void**)&w1, g_w1);  cudaGetSymbolAddress((void**)&w2, g_w2);
    cudaGetSymbolAddress((void**)&wi, g_wi);  cudaGetSymbolAddress((void**)&wp, g_wp);
    cudaGetSymbolAddress((void**)&xh, g_x);   cudaGetSymbolAddress((void**)&y, g_y);
    cudaGetSymbolAddress((void**)&qkvb, g_qkv);
    cudaGetSymbolAddress((void**)&z, g_z);    cudaGetSymbolAddress((void**)&hb, g_h);
    cudaGetSymbolAddress((void**)&pf, g_pf);
    cudaGetSymbolAddress((void**)&tok, g_tok); cudaGetSymbolAddress((void**)&ps, g_ps);
    cudaGetSymbolAddress((void**)&pooled, g_pooled); cudaGetSymbolAddress((void**)&pout, g_pout);

    static bool done = false;
    if (!done){
        cudaFuncSetAttribute(attn_k, cudaFuncAttributeMaxDynamicSharedMemorySize, ATTN_SMF*4);
        cudaFuncSetAttribute(gemm_p<0,false>, cudaFuncAttributeMaxDynamicSharedMemorySize, SM_G);
        cudaFuncSetAttribute(gemm_p<0,true >, cudaFuncAttributeMaxDynamicSharedMemorySize, SM_G);
        cudaFuncSetAttribute(gemm_p<1,true >, cudaFuncAttributeMaxDynamicSharedMemorySize, SM_G);
        cudaFuncSetAttribute(gemm_p<2,false>, cudaFuncAttributeMaxDynamicSharedMemorySize, SM_G);
        done = true;
    }

    dim3 blk(256);
    const long cvtBlocks = (NQ + NO + NF + NF + NO + NO)/4/256;  // 57344
    // [0] fused prep: x transpose + all weight conversions
    prep_k<<<(unsigned)(XTBLK + cvtBlocks), blk>>>(x, qkv_w, out_w, fc1w, fc2w,
                                                   in_w, ppw, xh,
                                                   wq, wo, w1, w2, wi, wp);
    // [1] tokens = X @ in_w^T + b
    gemm_p<0,false><<<dim3(16,256), blk, SM_G>>>(xh, wi, in_b, tok, nullptr, nullptr, MT, DD, DD);
    // [2] y = LN1(tokens)
    ln_k<<<MT, blk>>>(tok, n1g, n1b, y);
    // [3] qkv = y @ qkv_w^T + b   <- ncu capture slot
    gemm_p<0,true><<<dim3(48,256), blk, SM_G>>>(y, wq, qkv_b, qkvb, nullptr, nullptr, MT, 3*DD, DD);
    // [4] attention
    attn_k<<<NB*8, blk, ATTN_SMF*4>>>(qkvb, relb, z);
    // [5] tokens += ga*(z @ out_w^T + b)
    gemm_p<2,false><<<dim3(16,256), blk, SM_G>>>(z, wo, out_b, tok, tok, ga, MT, DD, DD);
    // [6] y = LN2(tokens)
    ln_k<<<MT, blk>>>(tok, n2g, n2b, y);
    // [7] h = GELU(y @ fc1^T + b)
    gemm_p<1,true><<<dim3(64,256), blk, SM_G>>>(y, w1, fc1b, hb, nullptr, nullptr, MT, HID, DD);
    // [8] tokens += gm*(h @ fc2^T + b)
    gemm_p<2,false><<<dim3(16,256), blk, SM_G>>>(hb, w2, fc2b, tok, tok, gm, MT, DD, HID);
    // [9-10] pooling
    poolscore_k<<<MT, blk>>>(tok, pq, png, pnb, ps);
    poolcomb_k<<<NB, blk>>>(tok, ps, pooled, pf);
    // [11] pout = pooled @ pool_w^T + b
    gemm_p<0,false><<<dim3(16,4), blk, SM_G>>>(pf, wp, ppb, pout, nullptr, nullptr, NB, DD, DD);
    // [12] normalize
    norm_k<<<NB, blk>>>(pout, out);
}

// round 13
// speedup vs baseline: 1.0004x; 1.0004x over previous
#include <cuda_runtime.h>
#include <cuda_fp16.h>
#include <cstdint>
#include <math.h>

#define NB   512
#define DD   2048
#define HID  8192
#define MT   (NB*64)

typedef __half hf;
typedef uint16_t u16;

// ---------------- scratch ----------------------------------------------------
__device__ hf    g_wq [(size_t)3*DD*DD];
__device__ hf    g_wo [(size_t)DD*DD];
__device__ hf    g_w1 [(size_t)HID*DD];
__device__ hf    g_w2 [(size_t)DD*HID];
__device__ hf    g_wi [(size_t)DD*DD];
__device__ hf    g_wp [(size_t)DD*DD];
__device__ hf    g_x  [(size_t)MT*DD];
__device__ hf    g_y  [(size_t)MT*DD];
__device__ hf    g_qkv[(size_t)MT*3*DD];
__device__ hf    g_z  [(size_t)MT*DD];
__device__ hf    g_h  [(size_t)MT*HID];
__device__ hf    g_f  [(size_t)MT*DD];
__device__ hf    g_pf [(size_t)NB*DD];
__device__ float g_tok[(size_t)MT*DD];
__device__ float g_ps [MT];
__device__ float g_pooled[(size_t)NB*DD];
__device__ float g_pout  [(size_t)NB*DD];

// ---------------- helpers ----------------------------------------------------
__device__ __forceinline__ uint32_t s2u(const void* p){
    uint32_t a;
    asm("{ .reg .u64 t; cvta.to.shared.u64 t, %1; cvt.u32.u64 %0, t; }" : "=r"(a) : "l"(p));
    return a;
}
__device__ __forceinline__ void cpa16(uint32_t d, const void* s){
    asm volatile("cp.async.cg.shared.global [%0], [%1], 16;" :: "r"(d), "l"(s));
}
__device__ __forceinline__ void ldm4(uint32_t* r, uint32_t a){
    asm volatile("ldmatrix.sync.aligned.m8n8.x4.shared.b16 {%0,%1,%2,%3}, [%4];"
        : "=r"(r[0]), "=r"(r[1]), "=r"(r[2]), "=r"(r[3]) : "r"(a));
}
__device__ __forceinline__ void mmaf16(float* d, const uint32_t* a, uint32_t b0, uint32_t b1){
    asm volatile(
        "mma.sync.aligned.m16n8k16.row.col.f32.f16.f16.f32 "
        "{%0,%1,%2,%3},{%4,%5,%6,%7},{%8,%9},{%0,%1,%2,%3};"
        : "+f"(d[0]), "+f"(d[1]), "+f"(d[2]), "+f"(d[3])
        : "r"(a[0]), "r"(a[1]), "r"(a[2]), "r"(a[3]), "r"(b0), "r"(b1));
}

// ---------------- pipelined fp16 GEMM (bias-only epilogue) -------------------
// CTA tile 128x128x64, warp 32x64 (8 warps), 3-stage cp.async ring, 2 CTAs/SM,
// smem-staged coalesced epilogue.  SINGLE code path for all GEMMs: no EPI
// branches -> identical (proven-fast) register allocation everywhere.
#define STH 72
#define STG (128*STH)
#define STAGEB (2*STG*2)
#define SM_G (3*STAGEB)
#define CSTRIDE 129
template<bool OUTH>
__global__ void __launch_bounds__(256, 2)
gemm_p(const hf* __restrict__ A, const hf* __restrict__ W,
       const float* __restrict__ bias, void* __restrict__ Cv,
       int M, int N, int K)
{
    extern __shared__ u16 smb[];
    const uint32_t sbase = s2u(smb);

    const int tid = threadIdx.x, wid = tid>>5, lane = tid&31;
    const int wm = wid&3, wn = wid>>2;
    const int m0 = blockIdx.y<<7, n0 = blockIdx.x<<7;
    const int g = lane>>2, qt = lane&3;

    float acc[2][8][4];
#pragma unroll
    for (int i=0;i<2;i++)
#pragma unroll
        for (int j=0;j<8;j++)
#pragma unroll
            for (int c=0;c<4;c++) acc[i][j][c]=0.f;

    const int T = K>>6;
    auto stage = [&](int t, int s){
        const int kt = t<<6;
        const uint32_t ob = sbase + (uint32_t)s*STAGEB;
#pragma unroll
        for (int i=0;i<4;i++){
            int id = tid + i*256, rr = id>>3, c8 = id&7;
            uint32_t so = rr*144 + c8*16;
            const size_t go = (size_t)rr*K + kt + c8*8;
            cpa16(ob + so,           A + (size_t)m0*K + go);
            cpa16(ob + STG*2 + so,   W + (size_t)n0*K + go);
        }
        asm volatile("cp.async.commit_group;" ::: "memory");
    };

    stage(0, 0);
    stage(1, 1);
    int s = 0, s2 = 2;
    for (int t=0; t<T; t++){
        if (t+1 < T) asm volatile("cp.async.wait_group 1;" ::: "memory");
        else         asm volatile("cp.async.wait_group 0;" ::: "memory");
        __syncthreads();
        if (t+2 < T) stage(t+2, s2);

        const uint32_t ab = sbase + (uint32_t)s*STAGEB;
        const uint32_t bb = ab + STG*2;

        const int arow = wm*32 + (lane&15);
        const int brow = wn*64 + ((lane>>4)<<3) + (lane&7);
        const int acol8 = (lane>>4)*8;
        const int bcol8 = ((lane>>3)&1)*8;
#pragma unroll
        for (int ks=0; ks<4; ks++){
            uint32_t af[2][4], bfr[4][4];
            ldm4(af[0], ab + (arow*STH + ks*16 + acol8)*2);
            ldm4(af[1], ab + ((arow+16)*STH + ks*16 + acol8)*2);
#pragma unroll
            for (int p=0;p<4;p++)
                ldm4(bfr[p], bb + ((brow + p*16)*STH + ks*16 + bcol8)*2);
#pragma unroll
            for (int mt=0;mt<2;mt++)
#pragma unroll
                for (int nt=0;nt<8;nt++)
                    mmaf16(acc[mt][nt], af[mt], bfr[nt>>1][(nt&1)*2], bfr[nt>>1][(nt&1)*2+1]);
        }
        s  = (s ==2)?0:s +1;
        s2 = (s2==2)?0:s2+1;
    }

    // ---- phase 2: smem-staged coalesced epilogue (bias only) ----
    __syncthreads();
    float* cs = (float*)smb;
#pragma unroll
    for (int mt=0;mt<2;mt++)
#pragma unroll
        for (int nt=0;nt<8;nt++)
#pragma unroll
            for (int c=0;c<4;c++){
                int rl = wm*32 + mt*16 + g + ((c>>1)<<3);
                int cl = wn*64 + nt*8 + qt*2 + (c&1);
                cs[rl*CSTRIDE + cl] = acc[mt][nt][c];
            }
    __syncthreads();
#pragma unroll 4
    for (int it=0; it<32; it++){
        int idx = it*256 + tid;
        int rl = idx>>6, cp2 = (idx&63)*2;
        float v0 = cs[rl*CSTRIDE + cp2]     + bias[n0 + cp2];
        float v1 = cs[rl*CSTRIDE + cp2 + 1] + bias[n0 + cp2 + 1];
        size_t go = (size_t)(m0+rl)*N + n0 + cp2;
        if (OUTH) *(__half2*)((hf*)Cv + go) = __floats2half2_rn(v0, v1);
        else      *(float2*)((float*)Cv + go) = make_float2(v0, v1);
    }
}

// ---------------- elementwise epilogue kernels -------------------------------
// GELU in-place on fp16 buffer (8 halves per thread)
__global__ void __launch_bounds__(256)
gelu_k(hf* __restrict__ h, long n){
    long i = ((long)blockIdx.x*256 + threadIdx.x)*8;
    if (i >= n) return;
    uint4 v = *(uint4*)(h + i);
    uint32_t* w = (uint32_t*)&v;
#pragma unroll
    for (int j=0;j<4;j++){
        float2 f = __half22float2(*(__half2*)&w[j]);
        f.x = 0.5f*f.x*(1.f + erff(f.x*0.70710678118654752f));
        f.y = 0.5f*f.y*(1.f + erff(f.y*0.70710678118654752f));
        *(__half2*)&w[j] = __floats2half2_rn(f.x, f.y);
    }
    *(uint4*)(h + i) = v;
}
// tok += gam * f   (fp32 += gam * fp16), 4 per thread
__global__ void __launch_bounds__(256)
resid_k(float* __restrict__ tok, const hf* __restrict__ f,
        const float* __restrict__ gam, long n){
    long i = ((long)blockIdx.x*256 + threadIdx.x)*4;
    if (i >= n) return;
    const float gv = gam[0];
    float4 t = *(float4*)(tok + i);
    uint2 fv = *(uint2*)(f + i);
    float2 f0 = __half22float2(*(__half2*)&fv.x);
    float2 f1 = __half22float2(*(__half2*)&fv.y);
    t.x += gv*f0.x; t.y += gv*f0.y; t.z += gv*f1.x; t.w += gv*f1.y;
    *(float4*)(tok + i) = t;
}
// fused: tok += gam*zo; y = LN(tok_new)  (one block per row)
__global__ void __launch_bounds__(256)
resid_ln_k(float* __restrict__ tok, const hf* __restrict__ zo,
           const float* __restrict__ gam, const float* __restrict__ gw,
           const float* __restrict__ bw, hf* __restrict__ y)
{
    __shared__ float sb[16];
    const int row = blockIdx.x, tid = threadIdx.x;
    const float gv = gam[0];
    float* tp = tok + (size_t)row*DD;
    const hf* zp = zo + (size_t)row*DD;
    float v[8], s=0.f, q=0.f;
#pragma unroll
    for (int i=0;i<8;i++){
        int c = tid + 256*i;
        float t = tp[c] + gv*__half2float(zp[c]);
        v[i] = t; s += t; q += t*t;
    }
#pragma unroll
    for (int o=16;o;o>>=1){ s+=__shfl_xor_sync(~0u,s,o); q+=__shfl_xor_sync(~0u,q,o); }
    if ((tid&31)==0){ sb[tid>>5]=s; sb[8+(tid>>5)]=q; }
    __syncthreads();
    s=0.f; q=0.f;
#pragma unroll
    for (int w=0;w<8;w++){ s+=sb[w]; q+=sb[8+w]; }
    float mu = s*(1.f/DD), var = q*(1.f/DD)-mu*mu, rstd = rsqrtf(var+1e-5f);
#pragma unroll
    for (int i=0;i<8;i++){
        int c = tid + 256*i;
        tp[c] = v[i];
        y[(size_t)row*DD+c] = __float2half_rn((v[i]-mu)*rstd*gw[c]+bw[c]);
    }
}

// ---------------- fused prep: xT + ALL weight conversions --------------------
#define NQ  ((long)3*DD*DD)
#define NO  ((long)DD*DD)
#define NF  ((long)HID*DD)
#define XTBLK (32*NB)
__global__ void __launch_bounds__(256)
prep_k(const float* __restrict__ x,
       const float* __restrict__ qkvw, const float* __restrict__ outw,
       const float* __restrict__ f1, const float* __restrict__ f2,
       const float* __restrict__ inw, const float* __restrict__ ppw,
       hf* __restrict__ xo,
       hf* __restrict__ wq, hf* __restrict__ wo, hf* __restrict__ w1,
       hf* __restrict__ w2, hf* __restrict__ wi, hf* __restrict__ wp)
{
    __shared__ float T[64][65];
    const int tid = threadIdx.x;
    if (blockIdx.x < XTBLK){
        const int b = blockIdx.x >> 5, c0 = (blockIdx.x & 31)*64;
        {
            const int sx = tid&63, cc = tid>>6;
            const float* xp = x + ((size_t)b*DD + c0)*64;
#pragma unroll
            for (int p=0;p<16;p++){ int c = cc + p*4; T[c][sx] = xp[(size_t)c*64 + sx]; }
        }
        __syncthreads();
        {
            const int c = tid&63, s4 = tid>>6;
#pragma unroll
            for (int p=0;p<16;p++){
                int ss = s4 + p*4;
                xo[((size_t)b*64 + ss)*DD + c0 + c] = __float2half_rn(T[c][ss]);
            }
        }
        return;
    }
    long i = ((long)(blockIdx.x - XTBLK)*256 + tid)*4;
    const long e0=NQ, e1=e0+NO, e2=e1+NF, e3=e2+NF, e4=e3+NO, e5=e4+NO;
    const float* s; hf* d; long j;
    if      (i < e0){ s=qkvw; d=wq; j=i; }
    else if (i < e1){ s=outw; d=wo; j=i-e0; }
    else if (i < e2){ s=f1;   d=w1; j=i-e1; }
    else if (i < e3){ s=f2;   d=w2; j=i-e2; }
    else if (i < e4){ s=inw;  d=wi; j=i-e3; }
    else if (i < e5){ s=ppw;  d=wp; j=i-e4; }
    else return;
    float4 v = *(const float4*)(s+j);
    d[j]=__float2half_rn(v.x); d[j+1]=__float2half_rn(v.y);
    d[j+2]=__float2half_rn(v.z); d[j+3]=__float2half_rn(v.w);
}

// ---------------- LayerNorm fp32 -> fp16 -------------------------------------
__global__ void __launch_bounds__(256)
ln_k(const float* __restrict__ src, const float* __restrict__ gw,
     const float* __restrict__ bw, hf* __restrict__ dst)
{
    __shared__ float sb[16];
    const int row = blockIdx.x, tid = threadIdx.x;
    const float* p = src + (size_t)row*DD;
    float v[8], s=0.f, q=0.f;
#pragma unroll
    for (int i=0;i<8;i++){ v[i]=p[tid+256*i]; s+=v[i]; q+=v[i]*v[i]; }
#pragma unroll
    for (int o=16;o;o>>=1){ s+=__shfl_xor_sync(~0u,s,o); q+=__shfl_xor_sync(~0u,q,o); }
    if ((tid&31)==0){ sb[tid>>5]=s; sb[8+(tid>>5)]=q; }
    __syncthreads();
    s=0.f; q=0.f;
#pragma unroll
    for (int w=0;w<8;w++){ s+=sb[w]; q+=sb[8+w]; }
    float mu = s*(1.f/DD), var = q*(1.f/DD)-mu*mu, rstd = rsqrtf(var+1e-5f);
#pragma unroll
    for (int i=0;i<8;i++){
        int c = tid+256*i;
        dst[(size_t)row*DD+c] = __float2half_rn((v[i]-mu)*rstd*gw[c]+bw[c]);
    }
}

// ---------------- fused attention per (b,h) ----------------------------------
#define ATTN_SMF (64*257 + 32*257 + 64*65 + 240)
__global__ void __launch_bounds__(256)
attn_k(const hf* __restrict__ qkv, const float* __restrict__ relb, hf* __restrict__ z)
{
    extern __shared__ float smf[];
    float* Qs = smf;
    float* KV = smf + 64*257;
    float* Ss = KV + 32*257;
    float* bs = Ss + 64*65;

    const int tid = threadIdx.x;
    const int bb = blockIdx.x>>3, h = blockIdx.x&7;
    const size_t base = (size_t)bb*64*6144 + h*256;

    for (int i=tid;i<225;i+=256) bs[i] = relb[h*225+i];
    for (int l=0;l<64;l++)
        Qs[l*257+tid] = __half2float(qkv[base + (size_t)l*6144 + tid]);
    __syncthreads();

    const int ty = tid>>4, tx = tid&15;
    for (int c=0;c<2;c++){
        for (int j=0;j<32;j++)
            KV[j*257+tid] = __half2float(qkv[base + (size_t)(c*32+j)*6144 + 2048 + tid]);
        __syncthreads();
        float a[4][2] = {};
        for (int k=0;k<256;k++){
            float k0 = KV[(2*tx)*257+k], k1 = KV[(2*tx+1)*257+k];
#pragma unroll
            for (int i=0;i<4;i++){
                float qv = Qs[(4*ty+i)*257+k];
                a[i][0] += qv*k0; a[i][1] += qv*k1;
            }
        }
#pragma unroll
        for (int i=0;i<4;i++)
#pragma unroll
            for (int j=0;j<2;j++){
                int row = 4*ty+i, col = c*32+2*tx+j;
                int rel = ((row>>3)-(col>>3)+7)*15 + ((row&7)-(col&7)+7);
                Ss[row*65+col] = a[i][j]*0.0625f + bs[rel];
            }
        __syncthreads();
    }
    {
        int w = tid>>5, lane = tid&31;
        for (int rr=0;rr<8;rr++){
            int row = w*8+rr;
            float v0 = Ss[row*65+lane], v1 = Ss[row*65+32+lane];
            float m = fmaxf(v0, v1);
#pragma unroll
            for (int o=16;o;o>>=1) m = fmaxf(m, __shfl_xor_sync(~0u, m, o));
            float e0 = expf(v0-m), e1 = expf(v1-m), ss = e0+e1;
#pragma unroll
            for (int o=16;o;o>>=1) ss += __shfl_xor_sync(~0u, ss, o);
            float inv = 1.f/ss;
            Ss[row*65+lane] = e0*inv; Ss[row*65+32+lane] = e1*inv;
        }
    }
    __syncthreads();

    float o[4][16];
#pragma unroll
    for (int i=0;i<4;i++)
#pragma unroll
        for (int j=0;j<16;j++) o[i][j]=0.f;
    for (int c=0;c<2;c++){
        for (int j=0;j<32;j++)
            KV[j*257+tid] = __half2float(qkv[base + (size_t)(c*32+j)*6144 + 4096 + tid]);
        __syncthreads();
        for (int j32=0;j32<32;j32++){
            float pv[4];
#pragma unroll
            for (int i=0;i<4;i++) pv[i] = Ss[(4*ty+i)*65 + c*32 + j32];
#pragma unroll
            for (int jc=0;jc<16;jc++){
                int jj = (jc+tx)&15;
                float vv = KV[j32*257 + 16*tx + jj];
#pragma unroll
                for (int i=0;i<4;i++) o[i][jj] += pv[i]*vv;
            }
        }
        __syncthreads();
    }
    const size_t zb = ((size_t)bb*64)*2048 + h*256;
#pragma unroll
    for (int i=0;i<4;i++)
#pragma unroll
        for (int jj=0;jj<16;jj++)
            z[zb + (size_t)(4*ty+i)*2048 + 16*tx + jj] = __float2half_rn(o[i][jj]);
}

// ---------------- pooling ----------------------------------------------------
__global__ void __launch_bounds__(256)
poolscore_k(const float* __restrict__ tok, const float* __restrict__ q,
            const float* __restrict__ gw, const float* __restrict__ bw,
            float* __restrict__ out)
{
    __shared__ float sb[40];
    const int row = blockIdx.x, tid = threadIdx.x;
    const float* p = tok + (size_t)row*DD;
    float s=0, sq=0, sqgt=0, sqg=0, sqb=0;
#pragma unroll
    for (int i=0;i<8;i++){
        int c = tid+256*i;
        float tv = p[c], qg = q[c]*gw[c];
        s+=tv; sq+=tv*tv; sqgt+=qg*tv; sqg+=qg; sqb+=q[c]*bw[c];
    }
#pragma unroll
    for (int o=16;o;o>>=1){
        s+=__shfl_xor_sync(~0u,s,o); sq+=__shfl_xor_sync(~0u,sq,o);
        sqgt+=__shfl_xor_sync(~0u,sqgt,o); sqg+=__shfl_xor_sync(~0u,sqg,o);
        sqb+=__shfl_xor_sync(~0u,sqb,o);
    }
    int w = tid>>5;
    if ((tid&31)==0){ sb[w]=s; sb[8+w]=sq; sb[16+w]=sqgt; sb[24+w]=sqg; sb[32+w]=sqb; }
    __syncthreads();
    if (tid==0){
        s=sq=sqgt=sqg=sqb=0.f;
        for (int i=0;i<8;i++){ s+=sb[i]; sq+=sb[8+i]; sqgt+=sb[16+i]; sqg+=sb[24+i]; sqb+=sb[32+i]; }
        float mu = s*(1.f/DD), var = sq*(1.f/DD)-mu*mu, rstd = rsqrtf(var+1e-5f);
        out[row] = (rstd*(sqgt-mu*sqg)+sqb)*0.022097086912079608f;
    }
}
__global__ void __launch_bounds__(256)
poolcomb_k(const float* __restrict__ tok, const float* __restrict__ ps,
           float* __restrict__ pooled, hf* __restrict__ pooledh)
{
    __shared__ float pr[64];
    const int b = blockIdx.x, tid = threadIdx.x;
    if (tid==0){
        float m = -1e30f;
        for (int l=0;l<64;l++) m = fmaxf(m, ps[b*64+l]);
        float ss = 0.f;
        for (int l=0;l<64;l++){ pr[l] = expf(ps[b*64+l]-m); ss += pr[l]; }
        float inv = 1.f/ss;
        for (int l=0;l<64;l++) pr[l] *= inv;
    }
    __syncthreads();
    float acc[8] = {};
    for (int l=0;l<64;l++){
        float w = pr[l];
        const float* tp = tok + ((size_t)b*64+l)*DD;
#pragma unroll
        for (int i=0;i<8;i++) acc[i] += w*tp[tid+256*i];
    }
#pragma unroll
    for (int i=0;i<8;i++){
        pooled[(size_t)b*DD + tid+256*i] = acc[i];
        pooledh[(size_t)b*DD + tid+256*i] = __float2half_rn(acc[i]);
    }
}
__global__ void __launch_bounds__(256)
norm_k(const float* __restrict__ pin, float* __restrict__ out)
{
    __shared__ float sb[8];
    const int b = blockIdx.x, tid = threadIdx.x;
    const float* p = pin + (size_t)b*DD;
    float v[8], s = 0.f;
#pragma unroll
    for (int i=0;i<8;i++){ v[i]=p[tid+256*i]; s+=v[i]*v[i]; }
#pragma unroll
    for (int o=16;o;o>>=1) s += __shfl_xor_sync(~0u, s, o);
    if ((tid&31)==0) sb[tid>>5]=s;
    __syncthreads();
    s=0.f;
#pragma unroll
    for (int w=0;w<8;w++) s += sb[w];
    float sc = 1.f/fmaxf(sqrtf(s), 1e-12f);
#pragma unroll
    for (int i=0;i<8;i++) out[(size_t)b*DD + tid+256*i] = v[i]*sc;
}

// ---------------- launch ------------------------------------------------------
extern "C" void kernel_launch(void* const* d_in, const int* in_sizes, int n_in,
                              void* d_out, int out_size)
{
    const float* x     = (const float*)d_in[0];
    const float* in_w  = (const float*)d_in[1];
    const float* in_b  = (const float*)d_in[2];
    const float* qkv_w = (const float*)d_in[3];
    const float* qkv_b = (const float*)d_in[4];
    const float* out_w = (const float*)d_in[5];
    const float* out_b = (const float*)d_in[6];
    const float* relb  = (const float*)d_in[7];
    const float* n1g   = (const float*)d_in[8];
    const float* n1b   = (const float*)d_in[9];
    const float* n2g   = (const float*)d_in[10];
    const float* n2b   = (const float*)d_in[11];
    const float* fc1w  = (const float*)d_in[12];
    const float* fc1b  = (const float*)d_in[13];
    const float* fc2w  = (const float*)d_in[14];
    const float* fc2b  = (const float*)d_in[15];
    const float* ga    = (const float*)d_in[16];
    const float* gm    = (const float*)d_in[17];
    const float* pq    = (const float*)d_in[18];
    const float* png   = (const float*)d_in[19];
    const float* pnb   = (const float*)d_in[20];
    const float* ppw   = (const float*)d_in[21];
    const float* ppb   = (const float*)d_in[22];
    float* out = (float*)d_out;

    hf *wq,*wo,*w1,*w2,*wi,*wp,*xh,*y,*qkvb,*z,*hb,*f,*pf;
    float *tok,*ps,*pooled,*pout;
    cudaGetSymbolAddress((void**)&wq, g_wq);  cudaGetSymbolAddress((void**)&wo, g_wo);
    cudaGetSymbolAddress((void**)&w1, g_w1);  cudaGetSymbolAddress((void**)&w2, g_w2);
    cudaGetSymbolAddress((void**)&wi, g_wi);  cudaGetSymbolAddress((void**)&wp, g_wp);
    cudaGetSymbolAddress((void**)&xh, g_x);   cudaGetSymbolAddress((void**)&y, g_y);
    cudaGetSymbolAddress((void**)&qkvb, g_qkv);
    cudaGetSymbolAddress((void**)&z, g_z);    cudaGetSymbolAddress((void**)&hb, g_h);
    cudaGetSymbolAddress((void**)&f, g_f);    cudaGetSymbolAddress((void**)&pf, g_pf);
    cudaGetSymbolAddress((void**)&tok, g_tok); cudaGetSymbolAddress((void**)&ps, g_ps);
    cudaGetSymbolAddress((void**)&pooled, g_pooled); cudaGetSymbolAddress((void**)&pout, g_pout);

    static bool done = false;
    if (!done){
        cudaFuncSetAttribute(attn_k, cudaFuncAttributeMaxDynamicSharedMemorySize, ATTN_SMF*4);
        cudaFuncSetAttribute(gemm_p<false>, cudaFuncAttributeMaxDynamicSharedMemorySize, SM_G);
        cudaFuncSetAttribute(gemm_p<true >, cudaFuncAttributeMaxDynamicSharedMemorySize, SM_G);
        done = true;
    }

    dim3 blk(256);
    const long cvtBlocks = (NQ + NO + NF + NF + NO + NO)/4/256;
    // [0] fused prep
    prep_k<<<(unsigned)(XTBLK + cvtBlocks), blk>>>(x, qkv_w, out_w, fc1w, fc2w,
                                                   in_w, ppw, xh,
                                                   wq, wo, w1, w2, wi, wp);
    // [1] tokens = X @ in_w^T + b (fp32 out)
    gemm_p<false><<<dim3(16,256), blk, SM_G>>>(xh, wi, in_b, tok, MT, DD, DD);
    // [2] y = LN1(tokens)
    ln_k<<<MT, blk>>>(tok, n1g, n1b, y);
    // [3] qkv = y @ qkv_w^T + b
    gemm_p<true><<<dim3(48,256), blk, SM_G>>>(y, wq, qkv_b, qkvb, MT, 3*DD, DD);
    // [4] attention -> z
    attn_k<<<NB*8, blk, ATTN_SMF*4>>>(qkvb, relb, z);
    // [5] zo = z @ out_w^T + b (fp16, into g_f)
    gemm_p<true><<<dim3(16,256), blk, SM_G>>>(z, wo, out_b, f, MT, DD, DD);
    // [6] tok += ga*zo ; y = LN2(tok)
    resid_ln_k<<<MT, blk>>>(tok, f, ga, n2g, n2b, y);
    // [7] h = y @ fc1^T + b (fp16)
    gemm_p<true><<<dim3(64,256), blk, SM_G>>>(y, w1, fc1b, hb, MT, HID, DD);
    // [8] h = GELU(h) in-place
    gelu_k<<<(unsigned)(((long)MT*HID/8 + 255)/256), blk>>>(hb, (long)MT*HID);
    // [9] f = h @ fc2^T + b (fp16)
    gemm_p<true><<<dim3(16,256), blk, SM_G>>>(hb, w2, fc2b, f, MT, DD, HID);
    // [10] tok += gm*f
    resid_k<<<(unsigned)(((long)MT*DD/4 + 255)/256), blk>>>(tok, f, gm, (long)MT*DD);
    // [11-12] pooling
    poolscore_k<<<MT, blk>>>(tok, pq, png, pnb, ps);
    poolcomb_k<<<NB, blk>>>(tok, ps, pooled, pf);
    // [13] pout = pooled @ pool_w^T + b
    gemm_p<false><<<dim3(16,4), blk, SM_G>>>(pf, wp, ppb, pout, NB, DD, DD);
    // [14] normalize
    norm_k<<<NB, blk>>>(pout, out);
}

// round 14
// speedup vs baseline: 1.0057x; 1.0053x over previous
#include <cuda_runtime.h>
#include <cuda_fp16.h>
#include <cstdint>
#include <math.h>

#define NB   512
#define DD   2048
#define HID  8192
#define MT   (NB*64)

typedef __half hf;
typedef uint16_t u16;

// ---------------- scratch ----------------------------------------------------
__device__ hf    g_wq [(size_t)3*DD*DD];
__device__ hf    g_wo [(size_t)DD*DD];
__device__ hf    g_w1 [(size_t)HID*DD];
__device__ hf    g_w2 [(size_t)DD*HID];
__device__ hf    g_wi [(size_t)DD*DD];
__device__ hf    g_wp [(size_t)DD*DD];
__device__ hf    g_x  [(size_t)MT*DD];
__device__ hf    g_y  [(size_t)MT*DD];
__device__ hf    g_qkv[(size_t)MT*3*DD];
__device__ hf    g_z  [(size_t)MT*DD];
__device__ hf    g_h  [(size_t)MT*HID];
__device__ hf    g_pf [(size_t)NB*DD];
__device__ float g_tok[(size_t)MT*DD];
__device__ float g_ps [MT];
__device__ float g_pooled[(size_t)NB*DD];
__device__ float g_pout  [(size_t)NB*DD];

// ---------------- helpers ----------------------------------------------------
__device__ __forceinline__ uint32_t s2u(const void* p){
    uint32_t a;
    asm("{ .reg .u64 t; cvta.to.shared.u64 t, %1; cvt.u32.u64 %0, t; }" : "=r"(a) : "l"(p));
    return a;
}
__device__ __forceinline__ void cpa16(uint32_t d, const void* s){
    asm volatile("cp.async.cg.shared.global [%0], [%1], 16;" :: "r"(d), "l"(s));
}
__device__ __forceinline__ void ldm4(uint32_t* r, uint32_t a){
    asm volatile("ldmatrix.sync.aligned.m8n8.x4.shared.b16 {%0,%1,%2,%3}, [%4];"
        : "=r"(r[0]), "=r"(r[1]), "=r"(r[2]), "=r"(r[3]) : "r"(a));
}
__device__ __forceinline__ void mmaf16(float* d, const uint32_t* a, uint32_t b0, uint32_t b1){
    asm volatile(
        "mma.sync.aligned.m16n8k16.row.col.f32.f16.f16.f32 "
        "{%0,%1,%2,%3},{%4,%5,%6,%7},{%8,%9},{%0,%1,%2,%3};"
        : "+f"(d[0]), "+f"(d[1]), "+f"(d[2]), "+f"(d[3])
        : "r"(a[0]), "r"(a[1]), "r"(a[2]), "r"(a[3]), "r"(b0), "r"(b1));
}

// ---------------- pipelined fp16 GEMM + fused epilogue -----------------------
// CTA tile 128x128x64, warp 32x64, 3-stage ring, 2 CTAs/SM, smem-staged
// phase-2 epilogue (EPI: 0 +bias ; 1 GELU(+bias) ; 2 resid+gam*(+bias)).
// CTA-pair de-phasing: odd CTAs nanosleep ~1us once so co-resident CTAs hit
// barriers in antiphase (one CTA's mma covers the other's sync/stage window).
#define STH 72
#define STG (128*STH)
#define STAGEB (2*STG*2)
#define SM_G (3*STAGEB)
#define CSTRIDE 129
template<int EPI, bool OUTH>
__global__ void __launch_bounds__(256, 2)
gemm_p(const hf* __restrict__ A, const hf* __restrict__ W,
       const float* __restrict__ bias, void* __restrict__ Cv,
       const float* __restrict__ resid, const float* __restrict__ gam,
       int M, int N, int K)
{
    extern __shared__ u16 smb[];
    const uint32_t sbase = s2u(smb);

    if ((blockIdx.x + blockIdx.y) & 1)
        asm volatile("nanosleep.u32 1000;");

    const int tid = threadIdx.x, wid = tid>>5, lane = tid&31;
    const int wm = wid&3, wn = wid>>2;
    const int m0 = blockIdx.y<<7, n0 = blockIdx.x<<7;
    const int g = lane>>2, qt = lane&3;

    float acc[2][8][4];
#pragma unroll
    for (int i=0;i<2;i++)
#pragma unroll
        for (int j=0;j<8;j++)
#pragma unroll
            for (int c=0;c<4;c++) acc[i][j][c]=0.f;

    const int T = K>>6;
    auto stage = [&](int t, int s){
        const int kt = t<<6;
        const uint32_t ob = sbase + (uint32_t)s*STAGEB;
#pragma unroll
        for (int i=0;i<4;i++){
            int id = tid + i*256, rr = id>>3, c8 = id&7;
            uint32_t so = rr*144 + c8*16;
            const size_t go = (size_t)rr*K + kt + c8*8;
            cpa16(ob + so,           A + (size_t)m0*K + go);
            cpa16(ob + STG*2 + so,   W + (size_t)n0*K + go);
        }
        asm volatile("cp.async.commit_group;" ::: "memory");
    };

    stage(0, 0);
    stage(1, 1);
    int s = 0, s2 = 2;
    for (int t=0; t<T; t++){
        if (t+1 < T) asm volatile("cp.async.wait_group 1;" ::: "memory");
        else         asm volatile("cp.async.wait_group 0;" ::: "memory");
        __syncthreads();
        if (t+2 < T) stage(t+2, s2);

        const uint32_t ab = sbase + (uint32_t)s*STAGEB;
        const uint32_t bb = ab + STG*2;

        const int arow = wm*32 + (lane&15);
        const int brow = wn*64 + ((lane>>4)<<3) + (lane&7);
        const int acol8 = (lane>>4)*8;
        const int bcol8 = ((lane>>3)&1)*8;
#pragma unroll
        for (int ks=0; ks<4; ks++){
            uint32_t af[2][4], bfr[4][4];
            ldm4(af[0], ab + (arow*STH + ks*16 + acol8)*2);
            ldm4(af[1], ab + ((arow+16)*STH + ks*16 + acol8)*2);
#pragma unroll
            for (int p=0;p<4;p++)
                ldm4(bfr[p], bb + ((brow + p*16)*STH + ks*16 + bcol8)*2);
#pragma unroll
            for (int mt=0;mt<2;mt++)
#pragma unroll
                for (int nt=0;nt<8;nt++)
                    mmaf16(acc[mt][nt], af[mt], bfr[nt>>1][(nt&1)*2], bfr[nt>>1][(nt&1)*2+1]);
        }
        s  = (s ==2)?0:s +1;
        s2 = (s2==2)?0:s2+1;
    }

    // ---- phase 2: smem-staged coalesced epilogue ----
    __syncthreads();
    float* cs = (float*)smb;
#pragma unroll
    for (int mt=0;mt<2;mt++)
#pragma unroll
        for (int nt=0;nt<8;nt++)
#pragma unroll
            for (int c=0;c<4;c++){
                int rl = wm*32 + mt*16 + g + ((c>>1)<<3);
                int cl = wn*64 + nt*8 + qt*2 + (c&1);
                cs[rl*CSTRIDE + cl] = acc[mt][nt][c];
            }
    __syncthreads();

    const float gv = (EPI==2) ? gam[0] : 0.f;
#pragma unroll 4
    for (int it=0; it<32; it++){
        int idx = it*256 + tid;
        int rl = idx>>6, cp2 = (idx&63)*2;
        float v0 = cs[rl*CSTRIDE + cp2]     + bias[n0 + cp2];
        float v1 = cs[rl*CSTRIDE + cp2 + 1] + bias[n0 + cp2 + 1];
        if (EPI==1){
            v0 = 0.5f*v0*(1.f + erff(v0*0.70710678118654752f));
            v1 = 0.5f*v1*(1.f + erff(v1*0.70710678118654752f));
        }
        size_t go = (size_t)(m0+rl)*N + n0 + cp2;
        if (EPI==2){
            float2 rv = *(const float2*)(resid + go);
            v0 = rv.x + gv*v0; v1 = rv.y + gv*v1;
        }
        if (OUTH) *(__half2*)((hf*)Cv + go) = __floats2half2_rn(v0, v1);
        else      *(float2*)((float*)Cv + go) = make_float2(v0, v1);
    }
}

// ---------------- fused prep: xT + ALL weight conversions --------------------
#define NQ  ((long)3*DD*DD)
#define NO  ((long)DD*DD)
#define NF  ((long)HID*DD)
#define XTBLK (32*NB)
__global__ void __launch_bounds__(256)
prep_k(const float* __restrict__ x,
       const float* __restrict__ qkvw, const float* __restrict__ outw,
       const float* __restrict__ f1, const float* __restrict__ f2,
       const float* __restrict__ inw, const float* __restrict__ ppw,
       hf* __restrict__ xo,
       hf* __restrict__ wq, hf* __restrict__ wo, hf* __restrict__ w1,
       hf* __restrict__ w2, hf* __restrict__ wi, hf* __restrict__ wp)
{
    __shared__ float T[64][65];
    const int tid = threadIdx.x;
    if (blockIdx.x < XTBLK){
        const int b = blockIdx.x >> 5, c0 = (blockIdx.x & 31)*64;
        {
            const int sx = tid&63, cc = tid>>6;
            const float* xp = x + ((size_t)b*DD + c0)*64;
#pragma unroll
            for (int p=0;p<16;p++){ int c = cc + p*4; T[c][sx] = xp[(size_t)c*64 + sx]; }
        }
        __syncthreads();
        {
            const int c = tid&63, s4 = tid>>6;
#pragma unroll
            for (int p=0;p<16;p++){
                int ss = s4 + p*4;
                xo[((size_t)b*64 + ss)*DD + c0 + c] = __float2half_rn(T[c][ss]);
            }
        }
        return;
    }
    long i = ((long)(blockIdx.x - XTBLK)*256 + tid)*4;
    const long e0=NQ, e1=e0+NO, e2=e1+NF, e3=e2+NF, e4=e3+NO, e5=e4+NO;
    const float* s; hf* d; long j;
    if      (i < e0){ s=qkvw; d=wq; j=i; }
    else if (i < e1){ s=outw; d=wo; j=i-e0; }
    else if (i < e2){ s=f1;   d=w1; j=i-e1; }
    else if (i < e3){ s=f2;   d=w2; j=i-e2; }
    else if (i < e4){ s=inw;  d=wi; j=i-e3; }
    else if (i < e5){ s=ppw;  d=wp; j=i-e4; }
    else return;
    float4 v = *(const float4*)(s+j);
    d[j]=__float2half_rn(v.x); d[j+1]=__float2half_rn(v.y);
    d[j+2]=__float2half_rn(v.z); d[j+3]=__float2half_rn(v.w);
}

// ---------------- LayerNorm fp32 -> fp16 -------------------------------------
__global__ void __launch_bounds__(256)
ln_k(const float* __restrict__ src, const float* __restrict__ gw,
     const float* __restrict__ bw, hf* __restrict__ dst)
{
    __shared__ float sb[16];
    const int row = blockIdx.x, tid = threadIdx.x;
    const float* p = src + (size_t)row*DD;
    float v[8], s=0.f, q=0.f;
#pragma unroll
    for (int i=0;i<8;i++){ v[i]=p[tid+256*i]; s+=v[i]; q+=v[i]*v[i]; }
#pragma unroll
    for (int o=16;o;o>>=1){ s+=__shfl_xor_sync(~0u,s,o); q+=__shfl_xor_sync(~0u,q,o); }
    if ((tid&31)==0){ sb[tid>>5]=s; sb[8+(tid>>5)]=q; }
    __syncthreads();
    s=0.f; q=0.f;
#pragma unroll
    for (int w=0;w<8;w++){ s+=sb[w]; q+=sb[8+w]; }
    float mu = s*(1.f/DD), var = q*(1.f/DD)-mu*mu, rstd = rsqrtf(var+1e-5f);
#pragma unroll
    for (int i=0;i<8;i++){
        int c = tid+256*i;
        dst[(size_t)row*DD+c] = __float2half_rn((v[i]-mu)*rstd*gw[c]+bw[c]);
    }
}

// ---------------- fused attention per (b,h) ----------------------------------
#define ATTN_SMF (64*257 + 32*257 + 64*65 + 240)
__global__ void __launch_bounds__(256)
attn_k(const hf* __restrict__ qkv, const float* __restrict__ relb, hf* __restrict__ z)
{
    extern __shared__ float smf[];
    float* Qs = smf;
    float* KV = smf + 64*257;
    float* Ss = KV + 32*257;
    float* bs = Ss + 64*65;

    const int tid = threadIdx.x;
    const int bb = blockIdx.x>>3, h = blockIdx.x&7;
    const size_t base = (size_t)bb*64*6144 + h*256;

    for (int i=tid;i<225;i+=256) bs[i] = relb[h*225+i];
    for (int l=0;l<64;l++)
        Qs[l*257+tid] = __half2float(qkv[base + (size_t)l*6144 + tid]);
    __syncthreads();

    const int ty = tid>>4, tx = tid&15;
    for (int c=0;c<2;c++){
        for (int j=0;j<32;j++)
            KV[j*257+tid] = __half2float(qkv[base + (size_t)(c*32+j)*6144 + 2048 + tid]);
        __syncthreads();
        float a[4][2] = {};
        for (int k=0;k<256;k++){
            float k0 = KV[(2*tx)*257+k], k1 = KV[(2*tx+1)*257+k];
#pragma unroll
            for (int i=0;i<4;i++){
                float qv = Qs[(4*ty+i)*257+k];
                a[i][0] += qv*k0; a[i][1] += qv*k1;
            }
        }
#pragma unroll
        for (int i=0;i<4;i++)
#pragma unroll
            for (int j=0;j<2;j++){
                int row = 4*ty+i, col = c*32+2*tx+j;
                int rel = ((row>>3)-(col>>3)+7)*15 + ((row&7)-(col&7)+7);
                Ss[row*65+col] = a[i][j]*0.0625f + bs[rel];
            }
        __syncthreads();
    }
    {
        int w = tid>>5, lane = tid&31;
        for (int rr=0;rr<8;rr++){
            int row = w*8+rr;
            float v0 = Ss[row*65+lane], v1 = Ss[row*65+32+lane];
            float m = fmaxf(v0, v1);
#pragma unroll
            for (int o=16;o;o>>=1) m = fmaxf(m, __shfl_xor_sync(~0u, m, o));
            float e0 = expf(v0-m), e1 = expf(v1-m), ss = e0+e1;
#pragma unroll
            for (int o=16;o;o>>=1) ss += __shfl_xor_sync(~0u, ss, o);
            float inv = 1.f/ss;
            Ss[row*65+lane] = e0*inv; Ss[row*65+32+lane] = e1*inv;
        }
    }
    __syncthreads();

    float o[4][16];
#pragma unroll
    for (int i=0;i<4;i++)
#pragma unroll
        for (int j=0;j<16;j++) o[i][j]=0.f;
    for (int c=0;c<2;c++){
        for (int j=0;j<32;j++)
            KV[j*257+tid] = __half2float(qkv[base + (size_t)(c*32+j)*6144 + 4096 + tid]);
        __syncthreads();
        for (int j32=0;j32<32;j32++){
            float pv[4];
#pragma unroll
            for (int i=0;i<4;i++) pv[i] = Ss[(4*ty+i)*65 + c*32 + j32];
#pragma unroll
            for (int jc=0;jc<16;jc++){
                int jj = (jc+tx)&15;
                float vv = KV[j32*257 + 16*tx + jj];
#pragma unroll
                for (int i=0;i<4;i++) o[i][jj] += pv[i]*vv;
            }
        }
        __syncthreads();
    }
    const size_t zb = ((size_t)bb*64)*2048 + h*256;
#pragma unroll
    for (int i=0;i<4;i++)
#pragma unroll
        for (int jj=0;jj<16;jj++)
            z[zb + (size_t)(4*ty+i)*2048 + 16*tx + jj] = __float2half_rn(o[i][jj]);
}

// ---------------- pooling ----------------------------------------------------
__global__ void __launch_bounds__(256)
poolscore_k(const float* __restrict__ tok, const float* __restrict__ q,
            const float* __restrict__ gw, const float* __restrict__ bw,
            float* __restrict__ out)
{
    __shared__ float sb[40];
    const int row = blockIdx.x, tid = threadIdx.x;
    const float* p = tok + (size_t)row*DD;
    float s=0, sq=0, sqgt=0, sqg=0, sqb=0;
#pragma unroll
    for (int i=0;i<8;i++){
        int c = tid+256*i;
        float tv = p[c], qg = q[c]*gw[c];
        s+=tv; sq+=tv*tv; sqgt+=qg*tv; sqg+=qg; sqb+=q[c]*bw[c];
    }
#pragma unroll
    for (int o=16;o;o>>=1){
        s+=__shfl_xor_sync(~0u,s,o); sq+=__shfl_xor_sync(~0u,sq,o);
        sqgt+=__shfl_xor_sync(~0u,sqgt,o); sqg+=__shfl_xor_sync(~0u,sqg,o);
        sqb+=__shfl_xor_sync(~0u,sqb,o);
    }
    int w = tid>>5;
    if ((tid&31)==0){ sb[w]=s; sb[8+w]=sq; sb[16+w]=sqgt; sb[24+w]=sqg; sb[32+w]=sqb; }
    __syncthreads();
    if (tid==0){
        s=sq=sqgt=sqg=sqb=0.f;
        for (int i=0;i<8;i++){ s+=sb[i]; sq+=sb[8+i]; sqgt+=sb[16+i]; sqg+=sb[24+i]; sqb+=sb[32+i]; }
        float mu = s*(1.f/DD), var = sq*(1.f/DD)-mu*mu, rstd = rsqrtf(var+1e-5f);
        out[row] = (rstd*(sqgt-mu*sqg)+sqb)*0.022097086912079608f;
    }
}
__global__ void __launch_bounds__(256)
poolcomb_k(const float* __restrict__ tok, const float* __restrict__ ps,
           float* __restrict__ pooled, hf* __restrict__ pooledh)
{
    __shared__ float pr[64];
    const int b = blockIdx.x, tid = threadIdx.x;
    if (tid==0){
        float m = -1e30f;
        for (int l=0;l<64;l++) m = fmaxf(m, ps[b*64+l]);
        float ss = 0.f;
        for (int l=0;l<64;l++){ pr[l] = expf(ps[b*64+l]-m); ss += pr[l]; }
        float inv = 1.f/ss;
        for (int l=0;l<64;l++) pr[l] *= inv;
    }
    __syncthreads();
    float acc[8] = {};
    for (int l=0;l<64;l++){
        float w = pr[l];
        const float* tp = tok + ((size_t)b*64+l)*DD;
#pragma unroll
        for (int i=0;i<8;i++) acc[i] += w*tp[tid+256*i];
    }
#pragma unroll
    for (int i=0;i<8;i++){
        pooled[(size_t)b*DD + tid+256*i] = acc[i];
        pooledh[(size_t)b*DD + tid+256*i] = __float2half_rn(acc[i]);
    }
}
__global__ void __launch_bounds__(256)
norm_k(const float* __restrict__ pin, float* __restrict__ out)
{
    __shared__ float sb[8];
    const int b = blockIdx.x, tid = threadIdx.x;
    const float* p = pin + (size_t)b*DD;
    float v[8], s = 0.f;
#pragma unroll
    for (int i=0;i<8;i++){ v[i]=p[tid+256*i]; s+=v[i]*v[i]; }
#pragma unroll
    for (int o=16;o;o>>=1) s += __shfl_xor_sync(~0u, s, o);
    if ((tid&31)==0) sb[tid>>5]=s;
    __syncthreads();
    s=0.f;
#pragma unroll
    for (int w=0;w<8;w++) s += sb[w];
    float sc = 1.f/fmaxf(sqrtf(s), 1e-12f);
#pragma unroll
    for (int i=0;i<8;i++) out[(size_t)b*DD + tid+256*i] = v[i]*sc;
}

// ---------------- launch ------------------------------------------------------
extern "C" void kernel_launch(void* const* d_in, const int* in_sizes, int n_in,
                              void* d_out, int out_size)
{
    const float* x     = (const float*)d_in[0];
    const float* in_w  = (const float*)d_in[1];
    const float* in_b  = (const float*)d_in[2];
    const float* qkv_w = (const float*)d_in[3];
    const float* qkv_b = (const float*)d_in[4];
    const float* out_w = (const float*)d_in[5];
    const float* out_b = (const float*)d_in[6];
    const float* relb  = (const float*)d_in[7];
    const float* n1g   = (const float*)d_in[8];
    const float* n1b   = (const float*)d_in[9];
    const float* n2g   = (const float*)d_in[10];
    const float* n2b   = (const float*)d_in[11];
    const float* fc1w  = (const float*)d_in[12];
    const float* fc1b  = (const float*)d_in[13];
    const float* fc2w  = (const float*)d_in[14];
    const float* fc2b  = (const float*)d_in[15];
    const float* ga    = (const float*)d_in[16];
    const float* gm    = (const float*)d_in[17];
    const float* pq    = (const float*)d_in[18];
    const float* png   = (const float*)d_in[19];
    const float* pnb   = (const float*)d_in[20];
    const float* ppw   = (const float*)d_in[21];
    const float* ppb   = (const float*)d_in[22];
    float* out = (float*)d_out;

    hf *wq,*wo,*w1,*w2,*wi,*wp,*xh,*y,*qkvb,*z,*hb,*pf;
    float *tok,*ps,*pooled,*pout;
    cudaGetSymbolAddress((void**)&wq, g_wq);  cudaGetSymbolAddress((void**)&wo, g_wo);
    cudaGetSymbolAddress((void**)&w1, g_w1);  cudaGetSymbolAddress((void**)&w2, g_w2);
    cudaGetSymbolAddress((void**)&wi, g_wi);  cudaGetSymbolAddress((void**)&wp, g_wp);
    cudaGetSymbolAddress((void**)&xh, g_x);   cudaGetSymbolAddress((void**)&y, g_y);
    cudaGetSymbolAddress((void**)&qkvb, g_qkv);
    cudaGetSymbolAddress((void**)&z, g_z);    cudaGetSymbolAddress((void**)&hb, g_h);
    cudaGetSymbolAddress((void**)&pf, g_pf);
    cudaGetSymbolAddress((void**)&tok, g_tok); cudaGetSymbolAddress((void**)&ps, g_ps);
    cudaGetSymbolAddress((void**)&pooled, g_pooled); cudaGetSymbolAddress((void**)&pout, g_pout);

    static bool done = false;
    if (!done){
        cudaFuncSetAttribute(attn_k, cudaFuncAttributeMaxDynamicSharedMemorySize, ATTN_SMF*4);
        cudaFuncSetAttribute(gemm_p<0,false>, cudaFuncAttributeMaxDynamicSharedMemorySize, SM_G);
        cudaFuncSetAttribute(gemm_p<0,true >, cudaFuncAttributeMaxDynamicSharedMemorySize, SM_G);
        cudaFuncSetAttribute(gemm_p<1,true >, cudaFuncAttributeMaxDynamicSharedMemorySize, SM_G);
        cudaFuncSetAttribute(gemm_p<2,false>, cudaFuncAttributeMaxDynamicSharedMemorySize, SM_G);
        done = true;
    }

    dim3 blk(256);
    const long cvtBlocks = (NQ + NO + NF + NF + NO + NO)/4/256;
    // [0] fused prep
    prep_k<<<(unsigned)(XTBLK + cvtBlocks), blk>>>(x, qkv_w, out_w, fc1w, fc2w,
                                                   in_w, ppw, xh,
                                                   wq, wo, w1, w2, wi, wp);
    // [1] tokens = X @ in_w^T + b (fp32)
    gemm_p<0,false><<<dim3(16,256), blk, SM_G>>>(xh, wi, in_b, tok, nullptr, nullptr, MT, DD, DD);
    // [2] y = LN1(tokens)
    ln_k<<<MT, blk>>>(tok, n1g, n1b, y);
    // [3] qkv = y @ qkv_w^T + b   <- ncu capture slot
    gemm_p<0,true><<<dim3(48,256), blk, SM_G>>>(y, wq, qkv_b, qkvb, nullptr, nullptr, MT, 3*DD, DD);
    // [4] attention -> z
    attn_k<<<NB*8, blk, ATTN_SMF*4>>>(qkvb, relb, z);
    // [5] tok += ga*(z @ out_w^T + b)   (fused residual)
    gemm_p<2,false><<<dim3(16,256), blk, SM_G>>>(z, wo, out_b, tok, tok, ga, MT, DD, DD);
    // [6] y = LN2(tok)
    ln_k<<<MT, blk>>>(tok, n2g, n2b, y);
    // [7] h = GELU(y @ fc1^T + b)   (fused GELU)
    gemm_p<1,true><<<dim3(64,256), blk, SM_G>>>(y, w1, fc1b, hb, nullptr, nullptr, MT, HID, DD);
    // [8] tok += gm*(h @ fc2^T + b)   (fused residual)
    gemm_p<2,false><<<dim3(16,256), blk, SM_G>>>(hb, w2, fc2b, tok, tok, gm, MT, DD, HID);
    // [9-10] pooling
    poolscore_k<<<MT, blk>>>(tok, pq, png, pnb, ps);
    poolcomb_k<<<NB, blk>>>(tok, ps, pooled, pf);
    // [11] pout = pooled @ pool_w^T + b
    gemm_p<0,false><<<dim3(16,4), blk, SM_G>>>(pf, wp, ppb, pout, nullptr, nullptr, NB, DD, DD);
    // [12] normalize
    norm_k<<<NB, blk>>>(pout, out);
}